// round 7
// baseline (speedup 1.0000x reference)
#include <cuda_runtime.h>
#include <cstdint>

// p-bit Glauber sequential update, N=4096 spins, 16384 steps.
// K0: thr[t]=atanh(2u-1) zipped with idx  (tanh(F)>=r  <=>  F>=atanh(r))
// K1: F = J@m0 + h (parallel; warms L2 with 64MB J)
// K2: single CTA, 544 threads, warp-specialized pipeline:
//   - warp 0 ("evaluator") resolves a 32-step window entirely warp-
//     synchronously (no CTA barriers per flip): register ballots, shfl
//     broadcast, depth-2 scattered prefetch of J[.][my_i]; confirmed flips
//     appended to a smem list.
//   - warps 1..16 ("owners", 512 threads, 8 F elems each in registers)
//     concurrently apply the PREVIOUS window's flip list (rank-1 row
//     updates, batched 8 rows for MLP), then publish F_sh.
//   - evaluator starts window w from F_sh (state <= w-2) and catches up
//     window w-1's flips via an MLP gather of J columns (same fmaf order
//     as owners => bit-identical).
//   - sync: evaluator bar.arrive / owners bar.sync on named barrier 1
//     (owners publish F_sh only after evaluator's F_sh reads), plus ONE
//     __syncthreads per window.

#define NN      4096
#define NSTEPS  16384
#define W       32
#define TPB     544            // 1 evaluator warp + 16 owner warps
#define NOWN    512
#define FULLM   0xffffffffu

__device__ float  g_F[NN];
__device__ float2 g_TI[NSTEPS];   // {thr, idx-as-float-bits}

// ---------------------------------------------------------------------------
__global__ void prep_thresholds(const int* __restrict__ idx,
                                const float* __restrict__ u) {
    const int t = blockIdx.x * blockDim.x + threadIdx.x;
    if (t < NSTEPS) {
        const float r = 2.0f * u[t] - 1.0f;
        g_TI[t] = make_float2(atanhf(r), __int_as_float(idx[t]));
    }
}

// ---------------------------------------------------------------------------
__global__ void init_field(const float* __restrict__ J,
                           const float* __restrict__ h,
                           const float* __restrict__ m0) {
    const int row = blockIdx.x;
    const float4* __restrict__ Jr = reinterpret_cast<const float4*>(J) + (size_t)row * (NN / 4);
    const float4* __restrict__ M4 = reinterpret_cast<const float4*>(m0);

    float sum = 0.0f;
    for (int k = threadIdx.x; k < NN / 4; k += blockDim.x) {
        float4 a = Jr[k];
        float4 b = M4[k];
        sum += a.x * b.x + a.y * b.y + a.z * b.z + a.w * b.w;
    }
    #pragma unroll
    for (int off = 16; off; off >>= 1)
        sum += __shfl_xor_sync(FULLM, sum, off);

    __shared__ float ws[8];
    const int lane = threadIdx.x & 31;
    const int wid  = threadIdx.x >> 5;
    if (lane == 0) ws[wid] = sum;
    __syncthreads();
    if (threadIdx.x == 0) {
        float tot = 0.0f;
        #pragma unroll
        for (int w = 0; w < 8; w++) tot += ws[w];
        g_F[row] = tot + h[row];
    }
}

// ---------------------------------------------------------------------------
__global__ __launch_bounds__(TPB, 1)
void pbit_dynamics(const float* __restrict__ J,
                   const float* __restrict__ m0,
                   float*       __restrict__ out) {
    __shared__ float F_sh[NN];        // published state, lags by <=2 windows
    __shared__ float m_sh[NN];        // spins; touched only by evaluator warp
    __shared__ int   flist[2][W];     // ping-pong flip lists
    __shared__ int   fcnt[2];

    const int tid   = threadIdx.x;
    const int lane  = tid & 31;
    const bool is_ev = (tid < 32);
    const int otid  = tid - 32;       // owner index in [0,512)

    const float4* gF4 = reinterpret_cast<const float4*>(g_F);
    float4* F4 = reinterpret_cast<float4*>(F_sh);
    float4 Fa, Fb;
    if (!is_ev) {
        Fa = gF4[otid];
        Fb = gF4[otid + NOWN];
        F4[otid]        = Fa;
        F4[otid + NOWN] = Fb;
    }
    for (int k = tid; k < NN; k += TPB) m_sh[k] = m0[k];
    if (tid == 0) { fcnt[0] = 0; fcnt[1] = 0; }

    float2 tiPF = make_float2(0.0f, 0.0f);
    if (is_ev) tiPF = g_TI[lane];
    __syncthreads();

    int w = 0;
    for (int t = 0; t < NSTEPS; t += W, w ^= 1) {
        if (is_ev) {
            // ================= evaluator warp =================
            const float my_thr = tiPF.x;
            const int   my_i   = __float_as_int(tiPF.y);
            __syncwarp();                       // own-warp m_sh stores visible
            float fF   = F_sh[my_i];            // state <= w-2
            float my_m = m_sh[my_i];            // state <= w-1 (own writes)
            asm volatile("bar.arrive 1, %0;" :: "r"(TPB));   // release F_sh

            // ---- catch up window w-1's flips (same fmaf order as owners) ----
            const int np = fcnt[w ^ 1];
            if (np > 0) {
                int   e8[W];
                #pragma unroll
                for (int k = 0; k < W; k++)
                    e8[k] = (k < np) ? flist[w ^ 1][k] : 0;
                float jv8[W];
                #pragma unroll
                for (int k = 0; k < W; k++) {
                    jv8[k] = 0.0f;
                    if (k < np)
                        jv8[k] = __ldg(J + (size_t)(e8[k] & 0xFFFF) * NN + my_i);
                }
                #pragma unroll
                for (int k = 0; k < W; k++) {
                    const float dk = (k < np) ? ((e8[k] & (1 << 30)) ? 2.0f : -2.0f) : 0.0f;
                    fF = fmaf(jv8[k], dk, fF);
                }
            }
            if (t + W < NSTEPS) tiPF = g_TI[t + W + lane];   // next window TI

            // ---- initial decision ----
            bool spos = (fF >= my_thr);
            bool flip = spos != (my_m > 0.0f);
            unsigned fb  = __ballot_sync(FULLM, flip);
            unsigned sbm = __ballot_sync(FULLM, spos);

            // depth-2 prefetch seed
            int pA = -1, pB = -1;
            float jA = 0.0f, jB = 0.0f;
            {
                unsigned m1 = fb;
                if (m1) {
                    pA = __ffs(m1) - 1;
                    const int iA = __shfl_sync(FULLM, my_i, pA);
                    jA = __ldg(J + (size_t)iA * NN + my_i);
                    m1 &= m1 - 1;
                    if (m1) {
                        pB = __ffs(m1) - 1;
                        const int iB = __shfl_sync(FULLM, my_i, pB);
                        jB = __ldg(J + (size_t)iB * NN + my_i);
                    }
                }
            }

            int cnt = 0;
            while (fb) {
                const int   f1 = __ffs(fb) - 1;
                const int   i1 = __shfl_sync(FULLM, my_i, f1);
                const float s1 = ((sbm >> f1) & 1u) ? 1.0f : -1.0f;
                const float d  = 2.0f * s1;

                float jv;
                if (f1 == pA)      { jv = jA; pA = pB; jA = jB; pB = -1; }
                else if (f1 == pB) { jv = jB; pA = -1; pB = -1; }
                else               { jv = __ldg(J + (size_t)i1 * NN + my_i); }

                if (lane == f1) {
                    flist[w][cnt] = i1 | ((s1 > 0.0f) ? (1 << 30) : 0);
                    m_sh[i1] = s1;
                }
                cnt++;

                // refill prefetch slots from remaining mask
                unsigned mr = fb & (fb - 1);             // clear f1 (lowest bit)
                const int c2 = mr ? (__ffs(mr) - 1) : -1;
                unsigned mr2 = mr ? (mr & (mr - 1)) : 0;
                const int c3 = mr2 ? (__ffs(mr2) - 1) : -1;
                if (c2 >= 0) {
                    if (pA != c2) {
                        const int i2 = __shfl_sync(FULLM, my_i, c2);
                        jA = __ldg(J + (size_t)i2 * NN + my_i);
                        pA = c2;
                    }
                } else pA = -1;
                if (c3 >= 0) {
                    if (pB != c3) {
                        const int i3 = __shfl_sync(FULLM, my_i, c3);
                        jB = __ldg(J + (size_t)i3 * NN + my_i);
                        pB = c3;
                    }
                } else pB = -1;

                // apply flip to local field, re-decide unresolved lanes
                fF = fmaf(jv, d, fF);
                if (my_i == i1) my_m = s1;
                bool ns = false, nf = false;
                if (lane > f1) {
                    ns = (fF >= my_thr);
                    nf = ns != (my_m > 0.0f);
                }
                fb  = __ballot_sync(FULLM, nf);
                sbm = __ballot_sync(FULLM, ns);
            }
            if (lane == 0) fcnt[w] = cnt;
        } else {
            // ================= owner warps =================
            const int np = fcnt[w ^ 1];      // prev window's flips
            for (int kb = 0; kb < np; kb += 8) {
                int e8[8];
                #pragma unroll
                for (int j = 0; j < 8; j++)
                    e8[j] = (kb + j < np) ? flist[w ^ 1][kb + j] : 0;
                float4 r0[8], r1[8];
                float  dd[8];
                #pragma unroll
                for (int j = 0; j < 8; j++) {
                    if (kb + j < np) {
                        const int ik = e8[j] & 0xFFFF;
                        dd[j] = (e8[j] & (1 << 30)) ? 2.0f : -2.0f;
                        const float4* __restrict__ Jr =
                            reinterpret_cast<const float4*>(J) + (size_t)ik * (NN / 4);
                        r0[j] = Jr[otid];
                        r1[j] = Jr[otid + NOWN];
                    } else {
                        dd[j] = 0.0f;
                        r0[j] = make_float4(0.f, 0.f, 0.f, 0.f);
                        r1[j] = r0[j];
                    }
                }
                #pragma unroll
                for (int j = 0; j < 8; j++) {
                    Fa.x = fmaf(r0[j].x, dd[j], Fa.x);
                    Fa.y = fmaf(r0[j].y, dd[j], Fa.y);
                    Fa.z = fmaf(r0[j].z, dd[j], Fa.z);
                    Fa.w = fmaf(r0[j].w, dd[j], Fa.w);
                    Fb.x = fmaf(r1[j].x, dd[j], Fb.x);
                    Fb.y = fmaf(r1[j].y, dd[j], Fb.y);
                    Fb.z = fmaf(r1[j].z, dd[j], Fb.z);
                    Fb.w = fmaf(r1[j].w, dd[j], Fb.w);
                }
            }
            // wait until evaluator finished its F_sh reads, then publish
            asm volatile("bar.sync 1, %0;" :: "r"(TPB));
            if (np > 0) {
                F4[otid]        = Fa;
                F4[otid + NOWN] = Fb;
            }
        }
        __syncthreads();
    }

    for (int k = tid; k < NN; k += TPB)
        out[k] = m_sh[k];
}

// ---------------------------------------------------------------------------
extern "C" void kernel_launch(void* const* d_in, const int* in_sizes, int n_in,
                              void* d_out, int out_size) {
    const float* J  = (const float*)d_in[0];
    const float* h  = (const float*)d_in[1];
    const float* m0 = (const float*)d_in[2];
    const int*   idx= (const int*)  d_in[3];
    const float* u  = (const float*)d_in[4];
    float* out = (float*)d_out;

    prep_thresholds<<<NSTEPS / 256, 256>>>(idx, u);
    init_field<<<NN, 256>>>(J, h, m0);
    pbit_dynamics<<<1, TPB>>>(J, m0, out);
}

// round 8
// speedup vs baseline: 1.9328x; 1.9328x over previous
#include <cuda_runtime.h>
#include <cstdint>

// p-bit Glauber sequential update, N=4096 spins, 16384 steps.
// K0: thr[t]=atanh(2u-1) zipped with idx   (tanh(F)>=r <=> F>=atanh(r))
// K1: F = J@m0 + h (parallel; warms L2 with 64MB J)
// Kpack: pre-gathers, for every 32-step window w:
//        Jw[w][k][l] = J[idx(w,k)][idx(w,l)]      (within-window interactions)
//        Jc[w][k][l] = J[idx(w-1,k)][idx(w,l)]    (cross-window catch-up)
//        -> all scattered J traffic moves to a parallel kernel (~4us);
//           the sequential kernel reads only dense 4KB blocks.
// K2: single CTA (544 thr), warp-specialized, per window w:
//   evaluator (warp 0): fF = F_sh[my_i] (state <= w-2); catch up window
//     w-1's flips via Jc (register masks, ascending order == owner order,
//     bit-identical fmaf); resolve window w via Jw in smem: per flip ONE
//     conflict-free LDS + fmaf + ballot. Zero global loads in the loop.
//   owners (512 thr, F in registers, 8 elems each): apply window w-1's
//     flip list (rank-1 rows, MLP batches), stage Jw/Jc for window w+1
//     (coalesced 8KB), then bar.sync(1) against evaluator's bar.arrive(1)
//     and publish F_sh. ONE __syncthreads per window.

#define NN      4096
#define NSTEPS  16384
#define W       32
#define NWIN    (NSTEPS / W)      // 512
#define TPB     544               // 1 evaluator warp + 16 owner warps
#define NOWN    512
#define FULLM   0xffffffffu

__device__ float  g_F[NN];
__device__ float2 g_TI[NSTEPS];
__device__ float  g_Jw[NWIN * W * W];   // 2MB
__device__ float  g_Jc[NWIN * W * W];   // 2MB

// ---------------------------------------------------------------------------
__global__ void prep_thresholds(const int* __restrict__ idx,
                                const float* __restrict__ u) {
    const int t = blockIdx.x * blockDim.x + threadIdx.x;
    if (t < NSTEPS) {
        const float r = 2.0f * u[t] - 1.0f;
        g_TI[t] = make_float2(atanhf(r), __int_as_float(idx[t]));
    }
}

// ---------------------------------------------------------------------------
__global__ void pack_windows(const float* __restrict__ J,
                             const int* __restrict__ idx) {
    const int w = blockIdx.x;
    for (int e = threadIdx.x; e < W * W; e += blockDim.x) {
        const int k = e >> 5;
        const int l = e & 31;
        const int il = idx[w * W + l];
        const int ik = idx[w * W + k];
        g_Jw[w * W * W + e] = J[(size_t)ik * NN + il];
        float jc = 0.0f;
        if (w > 0) {
            const int ikp = idx[(w - 1) * W + k];
            jc = J[(size_t)ikp * NN + il];
        }
        g_Jc[w * W * W + e] = jc;
    }
}

// ---------------------------------------------------------------------------
__global__ void init_field(const float* __restrict__ J,
                           const float* __restrict__ h,
                           const float* __restrict__ m0) {
    const int row = blockIdx.x;
    const float4* __restrict__ Jr = reinterpret_cast<const float4*>(J) + (size_t)row * (NN / 4);
    const float4* __restrict__ M4 = reinterpret_cast<const float4*>(m0);

    float sum = 0.0f;
    for (int k = threadIdx.x; k < NN / 4; k += blockDim.x) {
        float4 a = Jr[k];
        float4 b = M4[k];
        sum += a.x * b.x + a.y * b.y + a.z * b.z + a.w * b.w;
    }
    #pragma unroll
    for (int off = 16; off; off >>= 1)
        sum += __shfl_xor_sync(FULLM, sum, off);

    __shared__ float ws[8];
    const int lane = threadIdx.x & 31;
    const int wid  = threadIdx.x >> 5;
    if (lane == 0) ws[wid] = sum;
    __syncthreads();
    if (threadIdx.x == 0) {
        float tot = 0.0f;
        #pragma unroll
        for (int w = 0; w < 8; w++) tot += ws[w];
        g_F[row] = tot + h[row];
    }
}

// ---------------------------------------------------------------------------
__global__ __launch_bounds__(TPB, 1)
void pbit_dynamics(const float* __restrict__ J,
                   const float* __restrict__ m0,
                   float*       __restrict__ out) {
    __shared__ float F_sh[NN];              // 16KB, published per window
    __shared__ signed char m_s8[NN];        // 4KB spins, evaluator-owned
    __shared__ float JwS[2][W * W];         // 8KB  double-buffered
    __shared__ float JcS[2][W * W];         // 8KB
    __shared__ int   flist[2][W];
    __shared__ int   fcnt[2];

    const int tid   = threadIdx.x;
    const int lane  = tid & 31;
    const bool is_ev = (tid < 32);
    const int otid  = tid - 32;

    const float4* gF4 = reinterpret_cast<const float4*>(g_F);
    float4* F4 = reinterpret_cast<float4*>(F_sh);
    float4 Fa, Fb;
    if (!is_ev) {
        Fa = gF4[otid];
        Fb = gF4[otid + NOWN];
        F4[otid]        = Fa;
        F4[otid + NOWN] = Fb;
    }
    for (int k = tid; k < NN; k += TPB)
        m_s8[k] = (m0[k] > 0.0f) ? 1 : -1;
    if (tid == 0) { fcnt[0] = 0; fcnt[1] = 0; }
    // prologue: stage window 0
    for (int e = tid; e < W * W; e += TPB) {
        JwS[0][e] = g_Jw[e];
        JcS[0][e] = g_Jc[e];
    }
    float2 tiPF = make_float2(0.0f, 0.0f);
    if (is_ev) tiPF = g_TI[lane];
    unsigned prevFlipM = 0, prevSignM = 0;
    __syncthreads();

    int par = 0;
    for (int t = 0; t < NSTEPS; t += W, par ^= 1) {
        if (is_ev) {
            // ================= evaluator warp =================
            const float my_thr = tiPF.x;
            const int   my_i   = __float_as_int(tiPF.y);
            float fF = F_sh[my_i];                       // state <= w-2
            signed char mi8 = m_s8[my_i];
            asm volatile("bar.arrive 1, %0;" :: "r"(TPB));   // release F_sh

            // catch up window w-1's flips (ascending == owner order)
            const float* JcP = JcS[par];
            unsigned mm = prevFlipM;
            while (mm) {
                const int k = __ffs(mm) - 1;
                mm &= mm - 1;
                const float dk = ((prevSignM >> k) & 1u) ? 2.0f : -2.0f;
                fF = fmaf(JcP[(k << 5) + lane], dk, fF);
            }
            if (t + W < NSTEPS) tiPF = g_TI[t + W + lane];

            bool my_pos = (mi8 > 0);
            bool spos = (fF >= my_thr);
            bool flip = spos != my_pos;
            unsigned fb  = __ballot_sync(FULLM, flip);
            unsigned sbm = __ballot_sync(FULLM, spos);

            const float* JwP = JwS[par];
            unsigned flipM = 0, signM = 0;
            int cnt = 0;
            while (fb) {
                const int  f1 = __ffs(fb) - 1;
                const bool s1pos = (sbm >> f1) & 1u;
                const float d = s1pos ? 2.0f : -2.0f;
                const float jv = JwP[(f1 << 5) + lane];  // conflict-free LDS
                const int   i1 = __shfl_sync(FULLM, my_i, f1);
                if (lane == f1) {
                    m_s8[i1] = s1pos ? 1 : -1;
                    flist[par][cnt] = i1 | (s1pos ? (1 << 30) : 0);
                }
                flipM |= (1u << f1);
                if (s1pos) signM |= (1u << f1);
                cnt++;

                fF = fmaf(jv, d, fF);
                if (my_i == i1) my_pos = s1pos;
                bool ns = false, nf = false;
                if (lane > f1) {
                    ns = (fF >= my_thr);
                    nf = ns != my_pos;
                }
                fb  = __ballot_sync(FULLM, nf);
                sbm = __ballot_sync(FULLM, ns);
            }
            if (lane == 0) fcnt[par] = cnt;
            prevFlipM = flipM;
            prevSignM = signM;
        } else {
            // ================= owner warps =================
            const int np = fcnt[par ^ 1];            // window w-1's flips
            for (int kb = 0; kb < np; kb += 4) {
                int   e4[4];
                float dd[4];
                float4 r0[4], r1[4];
                #pragma unroll
                for (int j = 0; j < 4; j++) {
                    const bool v = (kb + j < np);
                    e4[j] = v ? flist[par ^ 1][kb + j] : 0;
                    dd[j] = v ? ((e4[j] & (1 << 30)) ? 2.0f : -2.0f) : 0.0f;
                    const int ik = e4[j] & 0xFFFF;
                    const float4* __restrict__ Jr =
                        reinterpret_cast<const float4*>(J) + (size_t)ik * (NN / 4);
                    if (v) {
                        r0[j] = Jr[otid];
                        r1[j] = Jr[otid + NOWN];
                    } else {
                        r0[j] = make_float4(0.f, 0.f, 0.f, 0.f);
                        r1[j] = r0[j];
                    }
                }
                #pragma unroll
                for (int j = 0; j < 4; j++) {
                    Fa.x = fmaf(r0[j].x, dd[j], Fa.x);
                    Fa.y = fmaf(r0[j].y, dd[j], Fa.y);
                    Fa.z = fmaf(r0[j].z, dd[j], Fa.z);
                    Fa.w = fmaf(r0[j].w, dd[j], Fa.w);
                    Fb.x = fmaf(r1[j].x, dd[j], Fb.x);
                    Fb.y = fmaf(r1[j].y, dd[j], Fb.y);
                    Fb.z = fmaf(r1[j].z, dd[j], Fb.z);
                    Fb.w = fmaf(r1[j].w, dd[j], Fb.w);
                }
            }
            // stage window w+1 (coalesced 8KB)
            if (t + W < NSTEPS) {
                const size_t base = (size_t)((t + W) >> 5) * (W * W);  // (w+1)*1024
                const float* __restrict__ srcw = g_Jw + base;
                const float* __restrict__ srcc = g_Jc + base;
                #pragma unroll
                for (int e = 0; e < 2; e++) {
                    JwS[par ^ 1][otid + e * NOWN] = srcw[otid + e * NOWN];
                    JcS[par ^ 1][otid + e * NOWN] = srcc[otid + e * NOWN];
                }
            }
            // wait for evaluator's F_sh reads, then publish
            asm volatile("bar.sync 1, %0;" :: "r"(TPB));
            if (np > 0) {
                F4[otid]        = Fa;
                F4[otid + NOWN] = Fb;
            }
        }
        __syncthreads();
    }

    for (int k = tid; k < NN; k += TPB)
        out[k] = (float)m_s8[k];
}

// ---------------------------------------------------------------------------
extern "C" void kernel_launch(void* const* d_in, const int* in_sizes, int n_in,
                              void* d_out, int out_size) {
    const float* J  = (const float*)d_in[0];
    const float* h  = (const float*)d_in[1];
    const float* m0 = (const float*)d_in[2];
    const int*   idx= (const int*)  d_in[3];
    const float* u  = (const float*)d_in[4];
    float* out = (float*)d_out;

    prep_thresholds<<<NSTEPS / 256, 256>>>(idx, u);
    pack_windows<<<NWIN, 256>>>(J, idx);
    init_field<<<NN, 256>>>(J, h, m0);
    pbit_dynamics<<<1, TPB>>>(J, m0, out);
}